// round 8
// baseline (speedup 1.0000x reference)
#include <cuda_runtime.h>
#include <math.h>
#include <stdint.h>

#define NB 64
#define HH 56
#define HW (HH*HH)            // 3136
#define CIN 256
#define COUT 256
#define TAPS 9
#define EPSC 1e-5
#define NSLICE 8
#define PH 58                 // padded height
#define PWID 66               // padded width

#define ASTR 80               // smem row stride (64 data + 16 pad) -> conflict-free ldmatrix
#define ATILE (128*ASTR)      // 10240
#define BTILE (256*ASTR)      // 20480
#define STAGE (ATILE+BTILE)   // 30720
#define NSTAGE 3
#define SMEM_TOTAL (STAGE*NSTAGE)
#define NCHUNK 36             // 9 taps x 4 ci-quarters (K64 each)

__device__ float  g_scale[CIN];
__device__ float  g_shift[CIN];
__device__ double g_part[CIN*NSLICE*2];
__device__ __align__(16) int8_t g_x8s[(size_t)NB*PH*PWID*CIN];  // ~63 MB padded NHWC
__device__ __align__(16) int8_t g_w8s[TAPS*COUT*CIN];           // 576 KB [tap][co][ci]

// ---------------- PTX helpers (all non-arch-specific: sm_80+) ----------------
__device__ __forceinline__ uint32_t smem_u32(const void* p) {
    uint32_t a;
    asm("{ .reg .u64 t; cvta.to.shared.u64 t, %1; cvt.u32.u64 %0, t; }" : "=r"(a) : "l"(p));
    return a;
}
__device__ __forceinline__ void cp_async16(uint32_t dst, const void* src) {
    asm volatile("cp.async.cg.shared.global [%0], [%1], 16;" :: "r"(dst), "l"(src));
}
__device__ __forceinline__ void ldsm_x4(uint32_t* r, uint32_t a) {
    asm volatile("ldmatrix.sync.aligned.m8n8.x4.shared.b16 {%0,%1,%2,%3}, [%4];"
        : "=r"(r[0]), "=r"(r[1]), "=r"(r[2]), "=r"(r[3]) : "r"(a));
}
__device__ __forceinline__ void ldsm_x2(uint32_t* r, uint32_t a) {
    asm volatile("ldmatrix.sync.aligned.m8n8.x2.shared.b16 {%0,%1}, [%2];"
        : "=r"(r[0]), "=r"(r[1]) : "r"(a));
}
__device__ __forceinline__ void mma_s8(int* d, const uint32_t* a, const uint32_t* b) {
    asm volatile("mma.sync.aligned.m16n8k32.row.col.s32.s8.s8.s32 "
        "{%0,%1,%2,%3}, {%4,%5,%6,%7}, {%8,%9}, {%0,%1,%2,%3};"
        : "+r"(d[0]), "+r"(d[1]), "+r"(d[2]), "+r"(d[3])
        : "r"(a[0]), "r"(a[1]), "r"(a[2]), "r"(a[3]), "r"(b[0]), "r"(b[1]));
}

// ---------------- 1) BN stats (two-stage, double accumulation) ----------------
__global__ void bn_stats1_kernel(const float* __restrict__ x) {
    const int c = blockIdx.x, slice = blockIdx.y, nper = NB/NSLICE;
    double s = 0.0, s2 = 0.0;
    for (int n = slice*nper; n < (slice+1)*nper; ++n) {
        const float4* p = (const float4*)(x + ((size_t)n*CIN + c)*HW);
        for (int i = threadIdx.x; i < HW/4; i += blockDim.x) {
            float4 v = p[i];
            s  += (double)v.x + (double)v.y + (double)v.z + (double)v.w;
            s2 += (double)v.x*v.x + (double)v.y*v.y + (double)v.z*v.z + (double)v.w*v.w;
        }
    }
    __shared__ double ws[32], ws2[32];
    #pragma unroll
    for (int o = 16; o > 0; o >>= 1) {
        s  += __shfl_down_sync(0xffffffffu, s,  o);
        s2 += __shfl_down_sync(0xffffffffu, s2, o);
    }
    const int warp = threadIdx.x>>5, lane = threadIdx.x&31;
    if (lane == 0) { ws[warp] = s; ws2[warp] = s2; }
    __syncthreads();
    if (warp == 0) {
        const int nw = blockDim.x>>5;
        s  = (lane < nw) ? ws[lane]  : 0.0;
        s2 = (lane < nw) ? ws2[lane] : 0.0;
        #pragma unroll
        for (int o = 16; o > 0; o >>= 1) {
            s  += __shfl_down_sync(0xffffffffu, s,  o);
            s2 += __shfl_down_sync(0xffffffffu, s2, o);
        }
        if (lane == 0) {
            g_part[(c*NSLICE+slice)*2+0] = s;
            g_part[(c*NSLICE+slice)*2+1] = s2;
        }
    }
}
__global__ void bn_stats2_kernel(const float* __restrict__ gamma, const float* __restrict__ beta) {
    const int c = blockIdx.x*blockDim.x + threadIdx.x;
    if (c >= CIN) return;
    double s = 0.0, s2 = 0.0;
    #pragma unroll
    for (int k = 0; k < NSLICE; ++k) { s += g_part[(c*NSLICE+k)*2]; s2 += g_part[(c*NSLICE+k)*2+1]; }
    const double Nt = (double)NB*(double)HW;
    double mean = s/Nt, var = s2/Nt - mean*mean;
    float sc = (float)(1.0/sqrt(var+EPSC)) * gamma[c];
    g_scale[c] = sc;
    g_shift[c] = beta[c] - (float)mean*sc;
}

// ---------------- 2) pack weights: g_w8s[tap][co][ci] = sign(w) as s8 ----------------
__global__ void pack_w_kernel(const float* __restrict__ w) {
    const int idx = blockIdx.x*blockDim.x + threadIdx.x;   // TAPS*COUT*64
    if (idx >= TAPS*COUT*64) return;
    const int ci4 = (idx & 63)*4, co = (idx>>6) & 255, tap = idx >> 14;
    union { int8_t b[4]; uint32_t u; } p;
    #pragma unroll
    for (int j = 0; j < 4; ++j) {
        float v = w[((size_t)co*CIN + ci4 + j)*TAPS + tap];
        p.b[j] = (v > 0.f) ? 1 : ((v < 0.f) ? -1 : 0);
    }
    *(uint32_t*)(g_w8s + ((size_t)(tap*COUT + co))*CIN + ci4) = p.u;
}

// ---------------- 3) pack x: padded NHWC s8 sign values (halo = 0) ----------------
__global__ void pack_x_kernel(const float* __restrict__ x) {
    const int idx = blockIdx.x*blockDim.x + threadIdx.x;   // NB*PH*8*PWID
    if (idx >= NB*PH*8*PWID) return;
    const int pw = idx % PWID;
    int t = idx / PWID;
    const int grp = t & 7;  t >>= 3;
    const int ph = t % PH;
    const int n  = t / PH;
    union { int8_t b[32]; uint4 u[2]; } p;
    const bool interior = (ph >= 1) & (ph <= HH) & (pw >= 1) & (pw <= HH);
    if (interior) {
        const int cb = grp*32;
        const float* q = x + ((size_t)n*CIN + cb)*HW + (ph-1)*HH + (pw-1);
        #pragma unroll
        for (int j = 0; j < 32; ++j) {
            float xh = fmaf(q[(size_t)j*HW], g_scale[cb+j], g_shift[cb+j]);
            p.b[j] = (xh > 0.f) ? 1 : ((xh < 0.f) ? -1 : 0);
        }
    } else {
        p.u[0] = make_uint4(0,0,0,0); p.u[1] = make_uint4(0,0,0,0);
    }
    uint4* dst = (uint4*)(g_x8s + ((size_t)(n*PH + ph)*PWID + pw)*CIN + grp*32);
    dst[0] = p.u[0]; dst[1] = p.u[1];
}

// ---------------- 4) IMMA implicit-GEMM conv + bias + ReLU ----------------
// CTA: 512 thr, tile M=128 px (2 rows x 64 lanes) x N=256 co. Warp 32x64.
// 36 K64 chunks, 3-stage cp.async pipeline, conflict-free ldmatrix (stride 80).
__global__ void __launch_bounds__(512, 1)
bconv_imma_kernel(const float* __restrict__ bias, float* __restrict__ out) {
    extern __shared__ char sm[];
    const uint32_t smb = smem_u32(sm);
    const int tid = threadIdx.x, wid = tid>>5, lane = tid&31;
    const int n = blockIdx.y, h0 = blockIdx.x*2;

    const int frow = tid>>2, fq = tid&3;          // fill: row, 16B quarter

    auto fill = [&](int s, int c) {
        const int tap = c>>2, cq = c&3;
        const int dh = tap/3 - 1, dw = tap%3 - 1;
        // A: 128 rows x 64B (one 16B quarter per thread)
        {
            const int oh = h0 + (frow>>6), ow = frow & 63;
            const int8_t* src = g_x8s
                + ((size_t)(n*PH + oh + 1 + dh)*PWID + ow + 1 + dw)*CIN + cq*64 + fq*16;
            cp_async16(smb + s*STAGE + frow*ASTR + fq*16, src);
        }
        // B: 256 rows x 64B (two rows per thread)
        #pragma unroll
        for (int i = 0; i < 2; ++i) {
            const int r2 = i*128 + frow;
            const int8_t* src = g_w8s + ((size_t)(tap*COUT + r2))*CIN + cq*64 + fq*16;
            cp_async16(smb + s*STAGE + ATILE + r2*ASTR + fq*16, src);
        }
    };

    int d[2][8][4];
    #pragma unroll
    for (int i = 0; i < 2; ++i)
        #pragma unroll
        for (int j = 0; j < 8; ++j)
            #pragma unroll
            for (int e = 0; e < 4; ++e) d[i][j][e] = 0;

    fill(0, 0); asm volatile("cp.async.commit_group;" ::: "memory");
    fill(1, 1); asm volatile("cp.async.commit_group;" ::: "memory");

    const int mw = wid>>2, nw = wid&3;

    for (int c = 0; c < NCHUNK; ++c) {
        const int s = c % 3;
        asm volatile("cp.async.wait_group 1;" ::: "memory");
        __syncthreads();
        const uint32_t A0 = smb + s*STAGE + (mw*32)*ASTR;
        const uint32_t B0 = smb + s*STAGE + ATILE + (nw*64)*ASTR;
        #pragma unroll
        for (int k = 0; k < 2; ++k) {              // two K32 steps in the K64 chunk
            uint32_t a[2][4];
            #pragma unroll
            for (int mt = 0; mt < 2; ++mt)
                ldsm_x4(a[mt], A0 + (mt*16 + (lane & 15))*ASTR + (k*2 + (lane>>4))*16);
            uint32_t b[8][2];
            #pragma unroll
            for (int nt = 0; nt < 8; ++nt)
                ldsm_x2(b[nt], B0 + (nt*8 + (lane & 7))*ASTR + (k*2 + ((lane>>3) & 1))*16);
            #pragma unroll
            for (int mt = 0; mt < 2; ++mt)
                #pragma unroll
                for (int nt = 0; nt < 8; ++nt)
                    mma_s8(d[mt][nt], a[mt], b[nt]);
        }
        if (c + 2 < NCHUNK) fill((c + 2) % 3, c + 2);
        asm volatile("cp.async.commit_group;" ::: "memory");
    }

    // epilogue: s32 -> f32 + bias + relu, scatter to NCHW out
    float bv[8][2];
    #pragma unroll
    for (int nt = 0; nt < 8; ++nt)
        #pragma unroll
        for (int cc = 0; cc < 2; ++cc)
            bv[nt][cc] = __ldg(bias + nw*64 + nt*8 + (lane & 3)*2 + cc);

    #pragma unroll
    for (int mt = 0; mt < 2; ++mt) {
        #pragma unroll
        for (int e2 = 0; e2 < 2; ++e2) {           // row halves (+0 / +8)
            const int row = mw*32 + mt*16 + (lane>>2) + e2*8;
            const int oh = h0 + (row>>6), ow = row & 63;
            if (ow < HH) {
                float* op = out + (size_t)n*COUT*HW + oh*HH + ow;
                #pragma unroll
                for (int nt = 0; nt < 8; ++nt) {
                    #pragma unroll
                    for (int cc = 0; cc < 2; ++cc) {
                        const int co = nw*64 + nt*8 + (lane & 3)*2 + cc;
                        const float y = (float)d[mt][nt][e2*2 + cc] + bv[nt][cc];
                        op[(size_t)co*HW] = fmaxf(y, 0.f);
                    }
                }
            }
        }
    }
}

// ---------------------------------------------------------------------------
extern "C" void kernel_launch(void* const* d_in, const int* in_sizes, int n_in,
                              void* d_out, int out_size) {
    const float* x     = (const float*)d_in[0];
    const float* gamma = (const float*)d_in[1];
    const float* beta  = (const float*)d_in[2];
    const float* w     = (const float*)d_in[3];
    const float* b     = (const float*)d_in[4];
    float* out = (float*)d_out;

    dim3 sgrid(CIN, NSLICE);
    bn_stats1_kernel<<<sgrid, 256>>>(x);
    bn_stats2_kernel<<<1, 256>>>(gamma, beta);

    pack_w_kernel<<<(TAPS*COUT*64 + 255)/256, 256>>>(w);

    const int pxn = NB*PH*8*PWID;
    pack_x_kernel<<<(pxn + 255)/256, 256>>>(x);

    cudaFuncSetAttribute(bconv_imma_kernel,
                         cudaFuncAttributeMaxDynamicSharedMemorySize, SMEM_TOTAL);
    dim3 grid(HH/2, NB);   // 28 x 64
    bconv_imma_kernel<<<grid, 512, SMEM_TOTAL>>>(b, out);
}

// round 11
// speedup vs baseline: 1.8642x; 1.8642x over previous
#include <cuda_runtime.h>
#include <math.h>
#include <stdint.h>

#define NB   64
#define CIN  256
#define COUT 256
#define HH   56
#define WWID 56
#define HW   (HH * WWID)       // 3136
#define NWORDS 8               // CIN / 32
#define TAPS 9
#define WPC  (TAPS * NWORDS)   // 72 words per output channel
#define EPSC 1e-5
#define NSLICE 8

__device__ float        g_scale[CIN];
__device__ float        g_shift[CIN];
__device__ double       g_part[CIN * NSLICE * 2];
__device__ unsigned int g_xbits[(size_t)NB * HW * NWORDS];   // ~6.4 MB
__device__ unsigned int g_wbits[COUT * WPC];
__device__ int          g_w9[COUT * TAPS];

// ---------------------------------------------------------------------------
// 1) BN stats stage 1: per (channel, batch-slice) partial sums (double).
// ---------------------------------------------------------------------------
__global__ void bn_stats1_kernel(const float* __restrict__ x) {
    const int c = blockIdx.x, slice = blockIdx.y, nper = NB / NSLICE;
    double s = 0.0, s2 = 0.0;
    for (int n = slice * nper; n < (slice + 1) * nper; ++n) {
        const float4* p = (const float4*)(x + ((size_t)n * CIN + c) * HW);
        for (int i = threadIdx.x; i < HW / 4; i += blockDim.x) {
            float4 v = p[i];
            s  += (double)v.x + (double)v.y + (double)v.z + (double)v.w;
            s2 += (double)v.x * v.x + (double)v.y * v.y + (double)v.z * v.z + (double)v.w * v.w;
        }
    }
    __shared__ double ws[32], ws2[32];
    #pragma unroll
    for (int o = 16; o > 0; o >>= 1) {
        s  += __shfl_down_sync(0xffffffffu, s,  o);
        s2 += __shfl_down_sync(0xffffffffu, s2, o);
    }
    const int warp = threadIdx.x >> 5, lane = threadIdx.x & 31;
    if (lane == 0) { ws[warp] = s; ws2[warp] = s2; }
    __syncthreads();
    if (warp == 0) {
        const int nw = blockDim.x >> 5;
        s  = (lane < nw) ? ws[lane]  : 0.0;
        s2 = (lane < nw) ? ws2[lane] : 0.0;
        #pragma unroll
        for (int o = 16; o > 0; o >>= 1) {
            s  += __shfl_down_sync(0xffffffffu, s,  o);
            s2 += __shfl_down_sync(0xffffffffu, s2, o);
        }
        if (lane == 0) {
            g_part[(c * NSLICE + slice) * 2 + 0] = s;
            g_part[(c * NSLICE + slice) * 2 + 1] = s2;
        }
    }
}

// ---------------------------------------------------------------------------
// 2) FUSED: weight bit-pack (+tap popcounts) AND bn stage-2 fold (block 0).
// ---------------------------------------------------------------------------
__global__ void packw_bn2_kernel(const float* __restrict__ w,
                                 const float* __restrict__ gamma,
                                 const float* __restrict__ beta) {
    // --- bn stage 2 (block 0 only; one channel per thread) ---
    if (blockIdx.x == 0 && threadIdx.x < CIN) {
        const int c = threadIdx.x;
        double s = 0.0, s2 = 0.0;
        #pragma unroll
        for (int k = 0; k < NSLICE; ++k) {
            s  += g_part[(c * NSLICE + k) * 2 + 0];
            s2 += g_part[(c * NSLICE + k) * 2 + 1];
        }
        const double Nt = (double)NB * (double)HW;
        double mean = s / Nt;
        double var  = s2 / Nt - mean * mean;
        float sc = (float)(1.0 / sqrt(var + EPSC)) * gamma[c];
        g_scale[c] = sc;
        g_shift[c] = beta[c] - (float)mean * sc;
    }
    // --- weight packing ---
    const int idx = blockIdx.x * blockDim.x + threadIdx.x;  // COUT*9*8 = 18432
    if (idx >= COUT * TAPS * NWORDS) return;
    const int word = idx & 7;
    const int tap  = (idx >> 3) % TAPS;
    const int co   = idx / (TAPS * NWORDS);
    const float* p = w + ((size_t)co * CIN + word * 32) * TAPS + tap;
    unsigned int bits = 0;
    #pragma unroll
    for (int j = 0; j < 32; ++j)
        if (p[(size_t)j * TAPS] > 0.0f) bits |= (1u << j);
    g_wbits[co * WPC + tap * NWORDS + word] = bits;
    int pc = __popc(bits);
    #pragma unroll
    for (int o = 4; o > 0; o >>= 1)
        pc += __shfl_down_sync(0xffffffffu, pc, o, 8);
    if (word == 0) g_w9[co * TAPS + tap] = pc;
}

// ---------------------------------------------------------------------------
// 3) Binarize + bit-pack activations: bit=1 iff BN(x) > 0.
// ---------------------------------------------------------------------------
__global__ void pack_x_kernel(const float* __restrict__ x) {
    const int idx = blockIdx.x * blockDim.x + threadIdx.x;
    if (idx >= NB * NWORDS * HW) return;
    const int s    = idx % HW;
    const int t    = idx / HW;
    const int word = t & 7;
    const int n    = t >> 3;
    const int cbase = word * 32;
    const float* p = x + ((size_t)(n * CIN + cbase)) * HW + s;
    unsigned int bits = 0;
    #pragma unroll
    for (int j = 0; j < 32; ++j) {
        float xh = fmaf(p[(size_t)j * HW], g_scale[cbase + j], g_shift[cbase + j]);
        if (xh > 0.0f) bits |= (1u << j);
    }
    g_xbits[((size_t)n * HW + s) * NWORDS + word] = bits;
}

// ---------------------------------------------------------------------------
// 4) XNOR-popcount conv + bias + ReLU. co-quad (16 accumulator chains).
// ---------------------------------------------------------------------------
#define CONV_THREADS 224
#define SMEM_CONV ((COUT * WPC + COUT * TAPS + COUT) * 4)

__global__ void __launch_bounds__(CONV_THREADS, 2)
bconv_kernel(const float* __restrict__ bias, float* __restrict__ out) {
    extern __shared__ unsigned int smem[];
    unsigned int* s_w  = smem;                       // COUT*72
    int*          s_w9 = (int*)(smem + COUT * WPC);  // COUT*9
    float*        s_b  = (float*)(smem + COUT * WPC + COUT * TAPS); // COUT

    const int tid = threadIdx.x;
    {
        const uint4* src = (const uint4*)g_wbits;
        uint4* dst = (uint4*)s_w;
        for (int i = tid; i < COUT * WPC / 4; i += CONV_THREADS) dst[i] = src[i];
    }
    for (int i = tid; i < COUT * TAPS; i += CONV_THREADS) s_w9[i] = g_w9[i];
    for (int i = tid; i < COUT; i += CONV_THREADS) s_b[i] = bias[i];
    __syncthreads();

    const int tx = tid % WWID;
    const int ty = tid / WWID;
    const int h  = blockIdx.x * 4 + ty;
    const int n  = blockIdx.y;

    const unsigned int* xb = g_xbits + (size_t)n * HW * NWORDS;

    unsigned int xr[WPC];
    unsigned int invmask = 0;
    #pragma unroll
    for (int dh = -1; dh <= 1; ++dh) {
        #pragma unroll
        for (int dw = -1; dw <= 1; ++dw) {
            const int tap = (dh + 1) * 3 + (dw + 1);
            const int hh = h + dh, ww = tx + dw;
            const bool valid = (hh >= 0) & (hh < HH) & (ww >= 0) & (ww < WWID);
            if (valid) {
                const uint4* p = (const uint4*)(xb + ((size_t)hh * WWID + ww) * NWORDS);
                uint4 a = p[0], b2 = p[1];
                xr[tap*8+0]=a.x;  xr[tap*8+1]=a.y;  xr[tap*8+2]=a.z;  xr[tap*8+3]=a.w;
                xr[tap*8+4]=b2.x; xr[tap*8+5]=b2.y; xr[tap*8+6]=b2.z; xr[tap*8+7]=b2.w;
            } else {
                invmask |= (1u << tap);
                #pragma unroll
                for (int k = 0; k < 8; ++k) xr[tap*8+k] = 0u;
            }
        }
    }
    const int nvalid = TAPS - __popc(invmask);
    const int base   = CIN * nvalid;

    int itap[5]; int nitap = 0;
    {
        unsigned int m = invmask;
        while (m) { itap[nitap++] = __ffs(m) - 1; m &= m - 1; }
    }

    float* outp = out + (size_t)n * COUT * HW + h * WWID + tx;

    for (int co = 0; co < COUT; co += 4) {
        const uint4* wpa = (const uint4*)(s_w + (co + 0) * WPC);
        const uint4* wpb = (const uint4*)(s_w + (co + 1) * WPC);
        const uint4* wpc = (const uint4*)(s_w + (co + 2) * WPC);
        const uint4* wpd = (const uint4*)(s_w + (co + 3) * WPC);
        int a0 = 0, a1 = 0, b0 = 0, b1 = 0;
        int c0 = 0, c1 = 0, d0 = 0, d1 = 0;
        #pragma unroll
        for (int t = 0; t < WPC / 4; ++t) {
            const uint4 wa = wpa[t];
            const uint4 wb = wpb[t];
            const uint4 wc = wpc[t];
            const uint4 wd = wpd[t];
            const unsigned int x0 = xr[4*t+0], x1 = xr[4*t+1];
            const unsigned int x2 = xr[4*t+2], x3 = xr[4*t+3];
            a0 += __popc(x0 ^ wa.x) + __popc(x1 ^ wa.y);
            a1 += __popc(x2 ^ wa.z) + __popc(x3 ^ wa.w);
            b0 += __popc(x0 ^ wb.x) + __popc(x1 ^ wb.y);
            b1 += __popc(x2 ^ wb.z) + __popc(x3 ^ wb.w);
            c0 += __popc(x0 ^ wc.x) + __popc(x1 ^ wc.y);
            c1 += __popc(x2 ^ wc.z) + __popc(x3 ^ wc.w);
            d0 += __popc(x0 ^ wd.x) + __popc(x1 ^ wd.y);
            d1 += __popc(x2 ^ wd.z) + __popc(x3 ^ wd.w);
        }
        int accA = a0 + a1, accB = b0 + b1, accC = c0 + c1, accD = d0 + d1;
        int corA = 0, corB = 0, corC = 0, corD = 0;
        if (nitap) {
            for (int k = 0; k < nitap; ++k) {
                const int tp = itap[k];
                corA += s_w9[(co + 0) * TAPS + tp];
                corB += s_w9[(co + 1) * TAPS + tp];
                corC += s_w9[(co + 2) * TAPS + tp];
                corD += s_w9[(co + 3) * TAPS + tp];
            }
        }
        float yA = (float)(base - 2 * accA + 2 * corA) + s_b[co + 0];
        float yB = (float)(base - 2 * accB + 2 * corB) + s_b[co + 1];
        float yC = (float)(base - 2 * accC + 2 * corC) + s_b[co + 2];
        float yD = (float)(base - 2 * accD + 2 * corD) + s_b[co + 3];
        outp[(size_t)(co + 0) * HW] = fmaxf(yA, 0.0f);
        outp[(size_t)(co + 1) * HW] = fmaxf(yB, 0.0f);
        outp[(size_t)(co + 2) * HW] = fmaxf(yC, 0.0f);
        outp[(size_t)(co + 3) * HW] = fmaxf(yD, 0.0f);
    }
}

// ---------------------------------------------------------------------------
extern "C" void kernel_launch(void* const* d_in, const int* in_sizes, int n_in,
                              void* d_out, int out_size) {
    const float* x     = (const float*)d_in[0];
    const float* gamma = (const float*)d_in[1];
    const float* beta  = (const float*)d_in[2];
    const float* w     = (const float*)d_in[3];
    const float* b     = (const float*)d_in[4];
    float* out = (float*)d_out;

    dim3 sgrid(CIN, NSLICE);
    bn_stats1_kernel<<<sgrid, 256>>>(x);                       // launch 0

    packw_bn2_kernel<<<(COUT*TAPS*NWORDS + 255)/256, 256>>>(w, gamma, beta); // launch 1

    const int pxn = NB * NWORDS * HW;
    pack_x_kernel<<<(pxn + 255)/256, 256>>>(x);                // launch 2

    cudaFuncSetAttribute(bconv_kernel,
                         cudaFuncAttributeMaxDynamicSharedMemorySize, SMEM_CONV);
    dim3 grid(HH / 4, NB);
    bconv_kernel<<<grid, CONV_THREADS, SMEM_CONV>>>(b, out);   // launch 3 (ncu target)
}

// round 12
// speedup vs baseline: 2.7117x; 1.4546x over previous
#include <cuda_runtime.h>
#include <math.h>
#include <stdint.h>

#define NB   64
#define CIN  256
#define COUT 256
#define HH   56
#define HW   (HH * HH)         // 3136
#define NWORDS 8
#define TAPS 9
#define KW   (TAPS * NWORDS)   // 72 k-words
#define EPSC 1e-5
#define NSLICE 8

__device__ float        g_scale[CIN];
__device__ float        g_shift[CIN];
__device__ double       g_part[CIN * NSLICE * 2];
__device__ unsigned int g_xbits[(size_t)NB * HW * NWORDS];     // [n][pix][word]
__device__ unsigned int g_wkt[KW * COUT];                      // k-major: [k][co]

// ---------------------------------------------------------------------------
// 1) BN stats stage 1: fp32 per-thread partials, double reduction.
// ---------------------------------------------------------------------------
__global__ void bn_stats1_kernel(const float* __restrict__ x) {
    const int c = blockIdx.x, slice = blockIdx.y, nper = NB / NSLICE;
    float fs = 0.f, fs2 = 0.f;
    for (int n = slice * nper; n < (slice + 1) * nper; ++n) {
        const float4* p = (const float4*)(x + ((size_t)n * CIN + c) * HW);
        for (int i = threadIdx.x; i < HW / 4; i += blockDim.x) {
            float4 v = p[i];
            fs  += v.x + v.y + v.z + v.w;
            fs2 += v.x * v.x + v.y * v.y + v.z * v.z + v.w * v.w;
        }
    }
    double s = (double)fs, s2 = (double)fs2;
    __shared__ double ws[32], ws2[32];
    #pragma unroll
    for (int o = 16; o > 0; o >>= 1) {
        s  += __shfl_down_sync(0xffffffffu, s,  o);
        s2 += __shfl_down_sync(0xffffffffu, s2, o);
    }
    const int warp = threadIdx.x >> 5, lane = threadIdx.x & 31;
    if (lane == 0) { ws[warp] = s; ws2[warp] = s2; }
    __syncthreads();
    if (warp == 0) {
        const int nw = blockDim.x >> 5;
        s  = (lane < nw) ? ws[lane]  : 0.0;
        s2 = (lane < nw) ? ws2[lane] : 0.0;
        #pragma unroll
        for (int o = 16; o > 0; o >>= 1) {
            s  += __shfl_down_sync(0xffffffffu, s,  o);
            s2 += __shfl_down_sync(0xffffffffu, s2, o);
        }
        if (lane == 0) {
            g_part[(c * NSLICE + slice) * 2 + 0] = s;
            g_part[(c * NSLICE + slice) * 2 + 1] = s2;
        }
    }
}

// ---------------------------------------------------------------------------
// 2) FUSED: weight bit-pack (k-major) AND bn stage-2 fold (block 0).
// ---------------------------------------------------------------------------
__global__ void packw_bn2_kernel(const float* __restrict__ w,
                                 const float* __restrict__ gamma,
                                 const float* __restrict__ beta) {
    if (blockIdx.x == 0 && threadIdx.x < CIN) {
        const int c = threadIdx.x;
        double s = 0.0, s2 = 0.0;
        #pragma unroll
        for (int k = 0; k < NSLICE; ++k) {
            s  += g_part[(c * NSLICE + k) * 2 + 0];
            s2 += g_part[(c * NSLICE + k) * 2 + 1];
        }
        const double Nt = (double)NB * (double)HW;
        double mean = s / Nt;
        double var  = s2 / Nt - mean * mean;
        float sc = (float)(1.0 / sqrt(var + EPSC)) * gamma[c];
        g_scale[c] = sc;
        g_shift[c] = beta[c] - (float)mean * sc;
    }
    const int idx = blockIdx.x * blockDim.x + threadIdx.x;   // COUT*72
    if (idx >= COUT * KW) return;
    const int word = idx & 7;
    const int tap  = (idx >> 3) % TAPS;
    const int co   = idx / KW;
    const float* p = w + ((size_t)co * CIN + word * 32) * TAPS + tap;
    unsigned int bits = 0;
    #pragma unroll
    for (int j = 0; j < 32; ++j)
        if (p[(size_t)j * TAPS] > 0.0f) bits |= (1u << j);
    g_wkt[(tap * NWORDS + word) * COUT + co] = bits;
}

// ---------------------------------------------------------------------------
// 3) Binarize + bit-pack activations.
// ---------------------------------------------------------------------------
__global__ void pack_x_kernel(const float* __restrict__ x) {
    const int idx = blockIdx.x * blockDim.x + threadIdx.x;
    if (idx >= NB * NWORDS * HW) return;
    const int s    = idx % HW;
    const int t    = idx / HW;
    const int word = t & 7;
    const int n    = t >> 3;
    const int cbase = word * 32;
    const float* p = x + ((size_t)(n * CIN + cbase)) * HW + s;
    unsigned int bits = 0;
    #pragma unroll
    for (int j = 0; j < 32; ++j) {
        float xh = fmaf(p[(size_t)j * HW], g_scale[cbase + j], g_shift[cbase + j]);
        if (xh > 0.0f) bits |= (1u << j);
    }
    g_xbits[((size_t)n * HW + s) * NWORDS + word] = bits;
}

// ---------------------------------------------------------------------------
// 4) GEMM-tiled XNOR-popcount conv.
//    Block: 64 pixels x 64 c_out, 256 threads, thread tile 4x4.
//    Borders via per-(tap,pix) validity mask: popc((x^w)&vm) — one LOP3.
// ---------------------------------------------------------------------------
#define MPIX 64
#define NCO  64
// smem words: xs 72*64, ws 72*64, vm 9*64, nv 64, bias 64
#define OFF_XS 0
#define OFF_WS (KW * MPIX)
#define OFF_VM (2 * KW * MPIX)
#define OFF_NV (2 * KW * MPIX + TAPS * MPIX)
#define OFF_SB (OFF_NV + MPIX)
#define SMEM_CONV ((OFF_SB + NCO) * 4)

__global__ void __launch_bounds__(256, 4)
bconv_kernel(const float* __restrict__ bias, float* __restrict__ out) {
    extern __shared__ unsigned int sm[];
    unsigned int* sxs = sm + OFF_XS;
    unsigned int* sws = sm + OFF_WS;
    unsigned int* svm = sm + OFF_VM;
    int*          snv = (int*)(sm + OFF_NV);
    float*        sb  = (float*)(sm + OFF_SB);

    const int tid = threadIdx.x;
    const int p0  = blockIdx.x * MPIX;
    const int co0 = blockIdx.y * NCO;
    const int n   = blockIdx.z;

    // fill weights (k-major sub-columns), vectorized
    {
        const uint4* src = (const uint4*)(g_wkt);
        uint4* dst = (uint4*)sws;
        // per k: 16 uint4 from row k at co0/4
        for (int i = tid; i < KW * (NCO / 4); i += 256) {
            const int k = i >> 4, q = i & 15;
            dst[k * 16 + q] = src[(k * COUT + co0) / 4 + q];
        }
    }
    // fill x im2col + validity masks
    const unsigned int* xb = g_xbits + (size_t)n * HW * NWORDS;
    for (int i = tid; i < KW * MPIX; i += 256) {
        const int k = i >> 6, j = i & 63;
        const int tap = k >> 3, word = k & 7;
        const int dh = tap / 3 - 1, dw = tap % 3 - 1;
        const int p = p0 + j;
        const int h = p / HH, w = p % HH;
        const int hh = h + dh, ww = w + dw;
        const bool valid = (hh >= 0) & (hh < HH) & (ww >= 0) & (ww < HH);
        sxs[i] = valid ? xb[((size_t)hh * HH + ww) * NWORDS + word] : 0u;
        if (word == 0) svm[tap * MPIX + j] = valid ? 0xffffffffu : 0u;
    }
    // nvalid per pixel + bias
    if (tid < MPIX) {
        const int p = p0 + tid;
        const int h = p / HH, w = p % HH;
        int nv = 0;
        #pragma unroll
        for (int tap = 0; tap < TAPS; ++tap) {
            const int hh = h + tap / 3 - 1, ww = w + tap % 3 - 1;
            nv += ((hh >= 0) & (hh < HH) & (ww >= 0) & (ww < HH)) ? 1 : 0;
        }
        snv[tid] = nv;
        sb[tid]  = bias[co0 + tid];
    }
    __syncthreads();

    const int pj = (tid & 15) * 4;   // pixel sub-tile
    const int cj = (tid >> 4) * 4;   // c_out sub-tile

    int acc[4][4];
    #pragma unroll
    for (int i = 0; i < 4; ++i)
        #pragma unroll
        for (int j = 0; j < 4; ++j) acc[i][j] = 0;

    #pragma unroll 1
    for (int tap = 0; tap < TAPS; ++tap) {
        const uint4 vm = *(const uint4*)(svm + tap * MPIX + pj);
        unsigned int va[4] = {vm.x, vm.y, vm.z, vm.w};
        #pragma unroll
        for (int wd = 0; wd < NWORDS; ++wd) {
            const int k = tap * NWORDS + wd;
            const uint4 xv = *(const uint4*)(sxs + k * MPIX + pj);
            const uint4 wv = *(const uint4*)(sws + k * NCO + cj);
            unsigned int xa[4] = {xv.x, xv.y, xv.z, xv.w};
            unsigned int wa[4] = {wv.x, wv.y, wv.z, wv.w};
            #pragma unroll
            for (int i = 0; i < 4; ++i)
                #pragma unroll
                for (int j = 0; j < 4; ++j)
                    acc[i][j] += __popc((xa[i] ^ wa[j]) & va[i]);
        }
    }

    // epilogue
    #pragma unroll
    for (int i = 0; i < 4; ++i) {
        const int p = p0 + pj + i;
        const int base = CIN * snv[pj + i];
        float* op = out + (size_t)n * COUT * HW + p;
        #pragma unroll
        for (int j = 0; j < 4; ++j) {
            const int co = cj + j;
            const float y = (float)(base - 2 * acc[i][j]) + sb[co];
            op[(size_t)(co0 + co) * HW] = fmaxf(y, 0.0f);
        }
    }
}

// ---------------------------------------------------------------------------
extern "C" void kernel_launch(void* const* d_in, const int* in_sizes, int n_in,
                              void* d_out, int out_size) {
    const float* x     = (const float*)d_in[0];
    const float* gamma = (const float*)d_in[1];
    const float* beta  = (const float*)d_in[2];
    const float* w     = (const float*)d_in[3];
    const float* b     = (const float*)d_in[4];
    float* out = (float*)d_out;

    dim3 sgrid(CIN, NSLICE);
    bn_stats1_kernel<<<sgrid, 256>>>(x);

    packw_bn2_kernel<<<(COUT * KW + 255) / 256, 256>>>(w, gamma, beta);

    const int pxn = NB * NWORDS * HW;
    pack_x_kernel<<<(pxn + 255) / 256, 256>>>(x);

    cudaFuncSetAttribute(bconv_kernel,
                         cudaFuncAttributeMaxDynamicSharedMemorySize, SMEM_CONV);
    dim3 grid(HW / MPIX, COUT / NCO, NB);   // 49 x 4 x 64
    bconv_kernel<<<grid, 256, SMEM_CONV>>>(b, out);
}